// round 1
// baseline (speedup 1.0000x reference)
#include <cuda_runtime.h>
#include <cuda_bf16.h>

// MMD loss: mean(XX + YY - XY - YX) over 5-kernel Gaussian RBF mixture.
// Restructured as a signed pairwise reduction over the 8192x8192 symmetric
// kernel matrix (upper block-triangle only), with closed-form bandwidth and
// the a + a^2 + a^4 + a^8 + a^16 single-exp trick.

#define NROWS 8192
#define NHALF 4096
#define DDIM  128

#define BM 128
#define BN 128
#define BK 32
#define NB (NROWS / BM)            // 64 row-blocks
#define NPAIRS (NB * (NB + 1) / 2) // 2080 upper-triangle block pairs

// ---- device scratch (no allocations allowed) ----
__device__ double g_S;              // sum of row squared norms
__device__ double g_colsum[DDIM];   // per-dim column sums
__device__ float  g_rowsq[NROWS];   // per-row squared norm
__device__ double g_acc;            // grand signed kernel sum
__device__ float  g_c;              // 1 / (16 * bw)

__global__ void k_init() {
    int t = threadIdx.x;
    if (t == 0) { g_S = 0.0; g_acc = 0.0; }
    if (t < DDIM) g_colsum[t] = 0.0;
}

// one warp per row: squared norm -> g_rowsq, and accumulate S
__global__ void k_rowstats(const float* __restrict__ src, const float* __restrict__ tgt) {
    int warp = threadIdx.x >> 5, lane = threadIdx.x & 31;
    int row = blockIdx.x * 8 + warp;
    const float* p = (row < NHALF) ? (src + (size_t)row * DDIM)
                                   : (tgt + (size_t)(row - NHALF) * DDIM);
    float4 v = ((const float4*)p)[lane];   // 32 lanes * 4 = 128 dims
    float sq = v.x * v.x + v.y * v.y + v.z * v.z + v.w * v.w;
    #pragma unroll
    for (int o = 16; o; o >>= 1) sq += __shfl_xor_sync(0xffffffffu, sq, o);
    if (lane == 0) {
        g_rowsq[row] = sq;
        atomicAdd(&g_S, (double)sq);
    }
}

// thread d accumulates column d over 128 rows per block
__global__ void k_colsum(const float* __restrict__ src, const float* __restrict__ tgt) {
    int d = threadIdx.x;
    int r0 = blockIdx.x * 128;
    const float* base = (r0 < NHALF) ? (src + (size_t)r0 * DDIM)
                                     : (tgt + (size_t)(r0 - NHALF) * DDIM);
    double acc = 0.0;
    #pragma unroll 4
    for (int r = 0; r < 128; r++) acc += base[(size_t)r * DDIM + d];
    atomicAdd(&g_colsum[d], acc);
}

// closed-form bandwidth -> scale
__global__ void k_scale() {
    __shared__ double sh[DDIM];
    int t = threadIdx.x;
    double c = g_colsum[t];
    sh[t] = c * c;
    __syncthreads();
    if (t == 0) {
        double T2 = 0.0;
        for (int i = 0; i < DDIM; i++) T2 += sh[i];
        double M = (double)NROWS;
        double bwsum = 2.0 * M * g_S - 2.0 * T2;
        double bw = bwsum / (M * M - M);
        bw = bw / 4.0;                      // KERNEL_MUL^(KERNEL_NUM//2) = 2^2
        g_c = (float)(1.0 / (16.0 * bw));   // widest kernel: bw * 2^4
    }
}

// main pairwise kernel: 128x128 tile Gram + fused RBF epilogue
__global__ __launch_bounds__(256, 2)
void k_main(const float* __restrict__ src, const float* __restrict__ tgt) {
    __shared__ float As[BK][BM + 4];
    __shared__ float Bs[BK][BN + 4];
    __shared__ float red[256];

    // map linear block id -> (bi, bj), bi <= bj
    int idx = blockIdx.x;
    int bi = 0, rem = idx;
    while (rem >= NB - bi) { rem -= NB - bi; bi++; }
    int bj = bi + rem;

    const float* Ap = (bi < NB / 2) ? (src + (size_t)bi * BM * DDIM)
                                    : (tgt + (size_t)(bi * BM - NHALF) * DDIM);
    const float* Bp = (bj < NB / 2) ? (src + (size_t)bj * BN * DDIM)
                                    : (tgt + (size_t)(bj * BN - NHALF) * DDIM);

    int tid = threadIdx.x;
    int ty = tid >> 4, tx = tid & 15;

    float acc[8][8];
    #pragma unroll
    for (int u = 0; u < 8; u++)
        #pragma unroll
        for (int v = 0; v < 8; v++) acc[u][v] = 0.0f;

    for (int kc = 0; kc < DDIM; kc += BK) {
        // load 128x32 chunks of A and B, transposed into [BK][BM]
        #pragma unroll
        for (int r = 0; r < 4; r++) {
            int f = tid + 256 * r;     // float4 index 0..1023
            int row = f >> 3;          // 0..127
            int c4 = f & 7;            // 0..7
            float4 va = ((const float4*)(Ap + (size_t)row * DDIM + kc))[c4];
            As[c4 * 4 + 0][row] = va.x;
            As[c4 * 4 + 1][row] = va.y;
            As[c4 * 4 + 2][row] = va.z;
            As[c4 * 4 + 3][row] = va.w;
            float4 vb = ((const float4*)(Bp + (size_t)row * DDIM + kc))[c4];
            Bs[c4 * 4 + 0][row] = vb.x;
            Bs[c4 * 4 + 1][row] = vb.y;
            Bs[c4 * 4 + 2][row] = vb.z;
            Bs[c4 * 4 + 3][row] = vb.w;
        }
        __syncthreads();

        #pragma unroll
        for (int k = 0; k < BK; k++) {
            float a[8], b[8];
            float4 a0 = *(const float4*)&As[k][ty * 8];
            float4 a1 = *(const float4*)&As[k][ty * 8 + 4];
            float4 b0 = *(const float4*)&Bs[k][tx * 8];
            float4 b1 = *(const float4*)&Bs[k][tx * 8 + 4];
            a[0]=a0.x; a[1]=a0.y; a[2]=a0.z; a[3]=a0.w;
            a[4]=a1.x; a[5]=a1.y; a[6]=a1.z; a[7]=a1.w;
            b[0]=b0.x; b[1]=b0.y; b[2]=b0.z; b[3]=b0.w;
            b[4]=b1.x; b[5]=b1.y; b[6]=b1.z; b[7]=b1.w;
            #pragma unroll
            for (int u = 0; u < 8; u++)
                #pragma unroll
                for (int v = 0; v < 8; v++)
                    acc[u][v] = fmaf(a[u], b[v], acc[u][v]);
        }
        __syncthreads();
    }

    // fused RBF epilogue: L2 -> a + a^2 + a^4 + a^8 + a^16
    float c = g_c;
    int row0 = bi * BM + ty * 8;
    int col0 = bj * BN + tx * 8;
    float rsA[8], rsB[8];
    #pragma unroll
    for (int u = 0; u < 8; u++) rsA[u] = g_rowsq[row0 + u];
    #pragma unroll
    for (int v = 0; v < 8; v++) rsB[v] = g_rowsq[col0 + v];

    float part = 0.0f;
    #pragma unroll
    for (int u = 0; u < 8; u++) {
        #pragma unroll
        for (int v = 0; v < 8; v++) {
            float L2 = rsA[u] + rsB[v] - 2.0f * acc[u][v];
            L2 = fmaxf(L2, 0.0f);
            float a1 = __expf(-L2 * c);
            float a2 = a1 * a1;
            float a4 = a2 * a2;
            float a8 = a4 * a4;
            float a16 = a8 * a8;
            part += a1 + a2 + a4 + a8 + a16;
        }
    }
    float w = ((bi < NB / 2) == (bj < NB / 2)) ? 1.0f : -1.0f;
    if (bi != bj) w *= 2.0f;   // off-diagonal block counted twice (symmetry)
    part *= w;

    // block reduce -> fp64 atomic
    red[tid] = part;
    __syncthreads();
    #pragma unroll
    for (int s = 128; s > 0; s >>= 1) {
        if (tid < s) red[tid] += red[tid + s];
        __syncthreads();
    }
    if (tid == 0) atomicAdd(&g_acc, (double)red[0]);
}

__global__ void k_final(float* out) {
    out[0] = (float)(g_acc / ((double)NHALF * (double)NHALF));
}

extern "C" void kernel_launch(void* const* d_in, const int* in_sizes, int n_in,
                              void* d_out, int out_size) {
    const float* src = (const float*)d_in[0];
    const float* tgt = (const float*)d_in[1];
    float* out = (float*)d_out;

    k_init<<<1, 128>>>();
    k_rowstats<<<NROWS / 8, 256>>>(src, tgt);
    k_colsum<<<NROWS / 128, 128>>>(src, tgt);
    k_scale<<<1, DDIM>>>();
    k_main<<<NPAIRS, 256>>>(src, tgt);
    k_final<<<1, 1>>>(out);
}

// round 5
// speedup vs baseline: 1.8763x; 1.8763x over previous
#include <cuda_runtime.h>
#include <cuda_bf16.h>
#include <cstdint>

// MMD loss: signed pairwise reduction over upper block-triangle of the
// 8192x8192 RBF kernel matrix. Gram via bf16 3-term split (hi*hi+hi*lo+lo*hi)
// on warp-level mma.sync (sm_80-compatible PTX -> legacy HMMA path), fused
// single-exp 5-kernel mixture epilogue.

#define NROWS 8192
#define NHALF 4096
#define DDIM  128

#define BM 128
#define BN 64                        // per-CTA column half
#define NB (NROWS / BM)              // 64
#define NPAIRS (NB * (NB + 1) / 2)   // 2080
#define NCTAS (NPAIRS * 2)           // 4160

#define SROW 272                     // padded row stride bytes (17 * 16B)
#define OFF_A_HI 0
#define OFF_A_LO (128 * SROW)            // 34816
#define OFF_B_HI (2 * 128 * SROW)        // 69632
#define OFF_B_LO (2 * 128 * SROW + 64 * SROW)
#define OFF_Q    (2 * 128 * SROW + 2 * 64 * SROW)   // 104448, 64 floats
#define OFF_RED  (OFF_Q + 256)                      // 256 floats
#define SMEM_DYN (OFF_RED + 1024)                   // 105728

// ---- device scratch ----
__device__ double g_S;
__device__ double g_colsum[DDIM];
__device__ float  g_rowsq[NROWS];
__device__ double g_acc;
__device__ float  g_c;
__device__ __align__(16) __nv_bfloat16 g_hi[NROWS * DDIM];
__device__ __align__(16) __nv_bfloat16 g_lo[NROWS * DDIM];

// ================= helpers =================
__device__ __forceinline__ uint32_t smem_u32(const void* p) {
    uint32_t a;
    asm("{ .reg .u64 t; cvta.to.shared.u64 t, %1; cvt.u32.u64 %0, t; }" : "=r"(a) : "l"(p));
    return a;
}
__device__ __forceinline__ float ex2f(float x) {
    float r; asm("ex2.approx.ftz.f32 %0, %1;" : "=f"(r) : "f"(x));
    return r;
}

#define LDSM_X4(r0, r1, r2, r3, addr) \
    asm volatile("ldmatrix.sync.aligned.m8n8.x4.shared.b16 {%0,%1,%2,%3}, [%4];" \
        : "=r"(r0), "=r"(r1), "=r"(r2), "=r"(r3) : "r"(addr))

#define MMA_BF16(d, a, b) \
    asm volatile("mma.sync.aligned.m16n8k16.row.col.f32.bf16.bf16.f32 " \
        "{%0,%1,%2,%3}, {%4,%5,%6,%7}, {%8,%9}, {%0,%1,%2,%3};" \
        : "+f"((d)[0]), "+f"((d)[1]), "+f"((d)[2]), "+f"((d)[3]) \
        : "r"((a)[0]), "r"((a)[1]), "r"((a)[2]), "r"((a)[3]), "r"((b)[0]), "r"((b)[1]))

// f32x2 packed ops
typedef unsigned long long u64t;
__device__ __forceinline__ u64t pk(float a, float b) {
    u64t r; asm("mov.b64 %0, {%1, %2};" : "=l"(r) : "f"(a), "f"(b)); return r;
}
__device__ __forceinline__ void unpk(float& a, float& b, u64t v) {
    asm("mov.b64 {%0, %1}, %2;" : "=f"(a), "=f"(b) : "l"(v));
}
__device__ __forceinline__ u64t pk_fma(u64t a, u64t b, u64t c) {
    u64t r; asm("fma.rn.f32x2 %0, %1, %2, %3;" : "=l"(r) : "l"(a), "l"(b), "l"(c)); return r;
}
__device__ __forceinline__ u64t pk_mul(u64t a, u64t b) {
    u64t r; asm("mul.rn.f32x2 %0, %1, %2;" : "=l"(r) : "l"(a), "l"(b)); return r;
}
__device__ __forceinline__ u64t pk_add(u64t a, u64t b) {
    u64t r; asm("add.rn.f32x2 %0, %1, %2;" : "=l"(r) : "l"(a), "l"(b)); return r;
}

// ================= prep kernels =================
__global__ void k_init() {
    int t = threadIdx.x;
    if (t == 0) { g_S = 0.0; g_acc = 0.0; }
    if (t < DDIM) g_colsum[t] = 0.0;
}

// one warp per row: rowsq + bf16 hi/lo split
__global__ void k_prep(const float* __restrict__ src, const float* __restrict__ tgt) {
    int warp = threadIdx.x >> 5, lane = threadIdx.x & 31;
    int row = blockIdx.x * 8 + warp;
    const float* p = (row < NHALF) ? (src + (size_t)row * DDIM)
                                   : (tgt + (size_t)(row - NHALF) * DDIM);
    float4 v = ((const float4*)p)[lane];

    float sq = v.x * v.x + v.y * v.y + v.z * v.z + v.w * v.w;
    #pragma unroll
    for (int o = 16; o; o >>= 1) sq += __shfl_xor_sync(0xffffffffu, sq, o);
    if (lane == 0) {
        g_rowsq[row] = sq;
        atomicAdd(&g_S, (double)sq);
    }

    __nv_bfloat16 h0 = __float2bfloat16_rn(v.x);
    __nv_bfloat16 h1 = __float2bfloat16_rn(v.y);
    __nv_bfloat16 h2 = __float2bfloat16_rn(v.z);
    __nv_bfloat16 h3 = __float2bfloat16_rn(v.w);
    __nv_bfloat16 l0 = __float2bfloat16_rn(v.x - __bfloat162float(h0));
    __nv_bfloat16 l1 = __float2bfloat16_rn(v.y - __bfloat162float(h1));
    __nv_bfloat16 l2 = __float2bfloat16_rn(v.z - __bfloat162float(h2));
    __nv_bfloat16 l3 = __float2bfloat16_rn(v.w - __bfloat162float(h3));

    uint2 ph, pl;
    ph.x = (uint32_t)__bfloat16_as_ushort(h0) | ((uint32_t)__bfloat16_as_ushort(h1) << 16);
    ph.y = (uint32_t)__bfloat16_as_ushort(h2) | ((uint32_t)__bfloat16_as_ushort(h3) << 16);
    pl.x = (uint32_t)__bfloat16_as_ushort(l0) | ((uint32_t)__bfloat16_as_ushort(l1) << 16);
    pl.y = (uint32_t)__bfloat16_as_ushort(l2) | ((uint32_t)__bfloat16_as_ushort(l3) << 16);
    *(uint2*)&g_hi[(size_t)row * DDIM + lane * 4] = ph;
    *(uint2*)&g_lo[(size_t)row * DDIM + lane * 4] = pl;
}

__global__ void k_colsum(const float* __restrict__ src, const float* __restrict__ tgt) {
    int d = threadIdx.x;
    int r0 = blockIdx.x * 128;
    const float* base = (r0 < NHALF) ? (src + (size_t)r0 * DDIM)
                                     : (tgt + (size_t)(r0 - NHALF) * DDIM);
    double acc = 0.0;
    #pragma unroll 4
    for (int r = 0; r < 128; r++) acc += base[(size_t)r * DDIM + d];
    atomicAdd(&g_colsum[d], acc);
}

__global__ void k_scale() {
    __shared__ double sh[DDIM];
    int t = threadIdx.x;
    double c = g_colsum[t];
    sh[t] = c * c;
    __syncthreads();
    if (t == 0) {
        double T2 = 0.0;
        for (int i = 0; i < DDIM; i++) T2 += sh[i];
        double M = (double)NROWS;
        double bw = (2.0 * M * g_S - 2.0 * T2) / (M * M - M);
        bw = bw / 4.0;                     // KERNEL_MUL^(KERNEL_NUM//2)
        g_c = (float)(1.0 / (16.0 * bw));  // widest kernel coefficient
    }
}

// ================= main kernel =================
__global__ void __launch_bounds__(256, 2)
k_main() {
    extern __shared__ __align__(16) char dsm[];
    uint32_t sb = smem_u32(dsm);

    int tid = threadIdx.x;
    int wid = tid >> 5, lane = tid & 31;

    // (bi, bj) pair + column-half mapping
    int pair = blockIdx.x >> 1;
    int half = blockIdx.x & 1;
    int bi = 0, rem = pair;
    while (rem >= NB - bi) { rem -= NB - bi; bi++; }
    int bj = bi + rem;

    int rowA0 = bi * 128;
    int rowB0 = bj * 128 + half * 64;

    // ---- stage A (128 rows) and B (64 rows), hi+lo, padded rows ----
    #pragma unroll
    for (int i = 0; i < 8; i++) {
        int f = tid + i * 256;          // 0..2047
        int r = f >> 4, c = f & 15;
        uint32_t dst = (uint32_t)(r * SROW + c * 16);
        size_t srcoff = (size_t)(rowA0 + r) * DDIM + c * 8;
        *(uint4*)(dsm + OFF_A_HI + dst) = *(const uint4*)&g_hi[srcoff];
        *(uint4*)(dsm + OFF_A_LO + dst) = *(const uint4*)&g_lo[srcoff];
    }
    #pragma unroll
    for (int i = 0; i < 4; i++) {
        int f = tid + i * 256;          // 0..1023
        int r = f >> 4, c = f & 15;
        uint32_t dst = (uint32_t)(r * SROW + c * 16);
        size_t srcoff = (size_t)(rowB0 + r) * DDIM + c * 8;
        *(uint4*)(dsm + OFF_B_HI + dst) = *(const uint4*)&g_hi[srcoff];
        *(uint4*)(dsm + OFF_B_LO + dst) = *(const uint4*)&g_lo[srcoff];
    }

    const float L2E = 1.4426950408889634f;
    float cfac = g_c;
    float nc2 = -cfac * L2E;
    if (tid < 64) {
        ((float*)(dsm + OFF_Q))[tid] = nc2 * g_rowsq[rowB0 + tid];
    }
    __syncthreads();

    // ---- warp-level GEMM: warp grid 4x2, warp tile 32x32 ----
    int warp_m = wid & 3;       // 0..3 -> rows
    int warp_n = wid >> 2;      // 0..1 -> cols
    int R = warp_m * 32;
    int C = warp_n * 32;

    int mat = lane >> 3;        // 0..3
    int rin = lane & 7;
    int mrow = (mat & 1) * 8 + rin;
    int mc16 = (mat >> 1) * 16;

    uint32_t aHiAddr[2], aLoAddr[2], bHiAddr[2], bLoAddr[2];
    #pragma unroll
    for (int mt = 0; mt < 2; mt++) {
        uint32_t off = (uint32_t)((R + mt * 16 + mrow) * SROW + mc16);
        aHiAddr[mt] = sb + OFF_A_HI + off;
        aLoAddr[mt] = sb + OFF_A_LO + off;
    }
    #pragma unroll
    for (int np = 0; np < 2; np++) {
        uint32_t off = (uint32_t)((C + np * 16 + mrow) * SROW + mc16);
        bHiAddr[np] = sb + OFF_B_HI + off;
        bLoAddr[np] = sb + OFF_B_LO + off;
    }

    float acc[2][4][4];
    #pragma unroll
    for (int mt = 0; mt < 2; mt++)
        #pragma unroll
        for (int nt = 0; nt < 4; nt++)
            #pragma unroll
            for (int r = 0; r < 4; r++) acc[mt][nt][r] = 0.0f;

    #pragma unroll
    for (int ks = 0; ks < 8; ks++) {
        uint32_t ko = ks * 32;
        uint32_t ah[2][4], al[2][4];
        uint32_t bh[4][2], bl[4][2];
        #pragma unroll
        for (int mt = 0; mt < 2; mt++) {
            LDSM_X4(ah[mt][0], ah[mt][1], ah[mt][2], ah[mt][3], aHiAddr[mt] + ko);
            LDSM_X4(al[mt][0], al[mt][1], al[mt][2], al[mt][3], aLoAddr[mt] + ko);
        }
        #pragma unroll
        for (int np = 0; np < 2; np++) {
            uint32_t r0, r1, r2, r3;
            LDSM_X4(r0, r1, r2, r3, bHiAddr[np] + ko);
            bh[np * 2 + 0][0] = r0; bh[np * 2 + 0][1] = r2;
            bh[np * 2 + 1][0] = r1; bh[np * 2 + 1][1] = r3;
            LDSM_X4(r0, r1, r2, r3, bLoAddr[np] + ko);
            bl[np * 2 + 0][0] = r0; bl[np * 2 + 0][1] = r2;
            bl[np * 2 + 1][0] = r1; bl[np * 2 + 1][1] = r3;
        }
        #pragma unroll
        for (int mt = 0; mt < 2; mt++) {
            #pragma unroll
            for (int nt = 0; nt < 4; nt++) {
                MMA_BF16(acc[mt][nt], ah[mt], bh[nt]);
                MMA_BF16(acc[mt][nt], ah[mt], bl[nt]);
                MMA_BF16(acc[mt][nt], al[mt], bh[nt]);
            }
        }
    }

    // ---- fused RBF epilogue ----
    float c2s = 2.0f * cfac * L2E;
    u64t c22 = pk(c2s, c2s);
    const float* qv = (const float*)(dsm + OFF_Q);

    // per-thread row indices: (mt, half8) -> row = R + mt*16 + h*8 + (lane>>2)
    u64t kA2[2][2];
    #pragma unroll
    for (int mt = 0; mt < 2; mt++)
        #pragma unroll
        for (int h = 0; h < 2; h++) {
            float kv = nc2 * g_rowsq[rowA0 + R + mt * 16 + h * 8 + (lane >> 2)];
            kA2[mt][h] = pk(kv, kv);
        }
    u64t q2[4];
    #pragma unroll
    for (int nt = 0; nt < 4; nt++)
        q2[nt] = *(const u64t*)(qv + C + nt * 8 + 2 * (lane & 3));

    u64t acc2 = pk(0.0f, 0.0f);
    #pragma unroll
    for (int mt = 0; mt < 2; mt++) {
        #pragma unroll
        for (int nt = 0; nt < 4; nt++) {
            #pragma unroll
            for (int h = 0; h < 2; h++) {
                u64t d2 = pk(acc[mt][nt][h * 2], acc[mt][nt][h * 2 + 1]);
                u64t arg = pk_fma(d2, c22, pk_add(q2[nt], kA2[mt][h]));
                float ax, bx; unpk(ax, bx, arg);
                u64t a1 = pk(ex2f(ax), ex2f(bx));
                u64t a2 = pk_mul(a1, a1);
                u64t a4 = pk_mul(a2, a2);
                u64t a8 = pk_mul(a4, a4);
                u64t u  = pk_fma(a8, a8, a8);   // a8 + a16
                u64t s  = pk_add(pk_add(u, a4), pk_add(a2, a1));
                acc2 = pk_add(acc2, s);
            }
        }
    }
    float plo, phi; unpk(plo, phi, acc2);
    float part = plo + phi;

    float w = ((bi < NB / 2) == (bj < NB / 2)) ? 1.0f : -1.0f;
    if (bi != bj) w *= 2.0f;
    part *= w;

    float* red = (float*)(dsm + OFF_RED);
    red[tid] = part;
    __syncthreads();
    #pragma unroll
    for (int s = 128; s > 0; s >>= 1) {
        if (tid < s) red[tid] += red[tid + s];
        __syncthreads();
    }
    if (tid == 0) atomicAdd(&g_acc, (double)red[0]);
}

__global__ void k_final(float* out) {
    out[0] = (float)(g_acc / ((double)NHALF * (double)NHALF));
}

extern "C" void kernel_launch(void* const* d_in, const int* in_sizes, int n_in,
                              void* d_out, int out_size) {
    const float* src = (const float*)d_in[0];
    const float* tgt = (const float*)d_in[1];
    float* out = (float*)d_out;

    cudaFuncSetAttribute(k_main, cudaFuncAttributeMaxDynamicSharedMemorySize, SMEM_DYN);

    k_init<<<1, 128>>>();
    k_prep<<<NROWS / 8, 256>>>(src, tgt);
    k_colsum<<<NROWS / 128, 128>>>(src, tgt);
    k_scale<<<1, DDIM>>>();
    k_main<<<NCTAS, 256, SMEM_DYN>>>();
    k_final<<<1, 1>>>(out);
}